// round 1
// baseline (speedup 1.0000x reference)
#include <cuda_runtime.h>
#include <cuda_bf16.h>

// out shape: (B=8, C=256, H=128, W=128) float32, row-major.
// out[b,c,i,j] = c<128 ? trig_c(i) : trig_{c-128}(j), batch-independent.
// trig_cc(p) = (cc even ? sin : cos)(p * 10000^(-floor(cc/2)/128))
//
// One block per (b,c) plane: compute the 128 unique values into smem,
// then stream 64 KiB of coalesced float4 stores.

__global__ __launch_bounds__(256) void pe2d_kernel(float* __restrict__ out) {
    const int bc  = blockIdx.x;       // b*256 + c
    const int c   = bc & 255;
    const int tid = threadIdx.x;

    __shared__ float s[128];

    if (tid < 128) {
        const int cc    = c & 127;        // channel within half
        const int pairk = cc >> 1;        // floor(cc/2)
        // inv_dim = 10000^(-pairk/128) = exp2(-pairk/128 * log2(10000))
        const float LOG2_10000 = 13.28771237954945f;
        float inv_dim = exp2f(-(float)pairk * (LOG2_10000 / 128.0f));
        float arg = (float)tid * inv_dim;  // tid plays the role of position (i or j)
        float sv, cv;
        sincosf(arg, &sv, &cv);
        s[tid] = (cc & 1) ? cv : sv;
    }
    __syncthreads();

    float4* outp = reinterpret_cast<float4*>(out) + (size_t)bc * 4096; // 128*128/4
    const float4* srow = reinterpret_cast<const float4*>(s);
    const bool lower = (c < 128);

    // 4096 float4 per plane, 256 threads -> 16 per thread, consecutive lanes
    // write consecutive float4 (fully coalesced 512B/warp).
    #pragma unroll
    for (int t = 0; t < 16; t++) {
        const int idx4 = tid + t * 256;
        float4 v;
        if (lower) {
            // value constant along j: broadcast s[i]
            const int i = idx4 >> 5;          // 32 float4 per row
            const float x = s[i];             // warp-uniform -> smem broadcast
            v = make_float4(x, x, x, x);
        } else {
            // value varies along j, constant along i: replicate the s row
            const int j4 = idx4 & 31;
            v = srow[j4];                     // conflict-free float4 LDS
        }
        outp[idx4] = v;
    }
}

extern "C" void kernel_launch(void* const* d_in, const int* in_sizes, int n_in,
                              void* d_out, int out_size) {
    (void)d_in; (void)in_sizes; (void)n_in; (void)out_size;
    // 8 batches * 256 channels = 2048 planes
    pe2d_kernel<<<2048, 256>>>((float*)d_out);
}